// round 13
// baseline (speedup 1.0000x reference)
#include <cuda_runtime.h>
#include <cuda_fp16.h>
#include <cstdint>

#define DEV __device__ __forceinline__

static constexpr int B_  = 8;
static constexpr int T_  = 4096;
static constexpr int D_  = 1024;
static constexpr int BT  = B_ * T_;        // 32768
static constexpr int N2  = 2 * D_;         // 2048
static constexpr int NCH = 64;
static constexpr int CL  = T_ / NCH;       // 64
static constexpr float LN_EPS = 1e-6f;

// pre-tiled operands: tile (blk, kt) = contiguous 4096 halves (8KB)
// element (row r 0..127, k-half kk 0..31): granule j=kk>>3, b=kk&7
// offset = ((blk*32+kt)*128 + r)*32 + ((j + (r>>1))&3)*8 + b   [halves]
__device__ __align__(16) __half g_xh[(size_t)BT * D_];   // x tiled fp16
__device__ __align__(16) __half g_wt[(size_t)N2 * D_];   // W^T tiled fp16
__device__ __align__(16) __half g_ch[(size_t)BT * D_];   // gate coeff (fp16, flat)
__device__ __align__(16) __half g_vh[(size_t)BT * D_];   // gate value (fp16, flat)
__device__ float g_A [B_ * NCH * D_];
__device__ float g_Hl[B_ * NCH * D_];
__device__ float g_Hp[B_ * NCH * D_];

DEV uint32_t smem_u32(const void* p) {
    uint32_t a;
    asm("{ .reg .u64 t; cvta.to.shared.u64 t, %1; cvt.u32.u64 %0, t; }" : "=r"(a) : "l"(p));
    return a;
}

#define MBAR_INIT(a, c) \
    asm volatile("mbarrier.init.shared.b64 [%0], %1;" :: "r"((uint32_t)(a)), "r"((uint32_t)(c)) : "memory")
#define MBAR_EXPECT_TX(a, tx) \
    asm volatile("mbarrier.arrive.expect_tx.shared.b64 _, [%0], %1;" :: "r"((uint32_t)(a)), "r"((uint32_t)(tx)) : "memory")
#define MBAR_WAIT(a, par) do {                                                             \
    uint32_t _m = (uint32_t)(a); uint32_t _p = (uint32_t)(par); uint32_t _d;               \
    asm volatile("{\n\t.reg .pred p;\n\t"                                                  \
        "mbarrier.try_wait.parity.acquire.cta.shared::cta.b64 p, [%1], %2;\n\t"            \
        "selp.b32 %0, 1, 0, p;\n\t}" : "=r"(_d) : "r"(_m), "r"(_p) : "memory");            \
    if (!_d) {                                                                             \
        asm volatile("{\n\t.reg .pred P1;\n\t"                                             \
            "WL_%=:\n\t"                                                                   \
            "mbarrier.try_wait.parity.acquire.cta.shared::cta.b64 P1, [%0], %1, 0x989680;\n\t" \
            "@P1 bra.uni WD_%=;\n\t bra.uni WL_%=;\n\t WD_%=:\n\t}"                        \
            :: "r"(_m), "r"(_p) : "memory");                                               \
    } } while (0)
#define BULK_G2S(dst, src, bytes, mbar) \
    asm volatile("cp.async.bulk.shared::cta.global.mbarrier::complete_tx::bytes [%0], [%1], %2, [%3];" \
        :: "r"((uint32_t)(dst)), "l"(src), "r"((uint32_t)(bytes)), "r"((uint32_t)(mbar)) : "memory")
#define FENCE_ASYNC() asm volatile("fence.proxy.async.shared::cta;" ::: "memory")

#define LDSM4(r0, r1, r2, r3, addr) \
    asm volatile("ldmatrix.sync.aligned.m8n8.x4.shared.b16 {%0,%1,%2,%3}, [%4];" \
        : "=r"(r0), "=r"(r1), "=r"(r2), "=r"(r3) : "r"(addr))

#define MMA(d, a0, a1, a2, a3, b0, b1) \
    asm volatile("mma.sync.aligned.m16n8k16.row.col.f32.f16.f16.f32 " \
        "{%0,%1,%2,%3}, {%4,%5,%6,%7}, {%8,%9}, {%0,%1,%2,%3};" \
        : "+f"((d)[0]), "+f"((d)[1]), "+f"((d)[2]), "+f"((d)[3]) \
        : "r"(a0), "r"(a1), "r"(a2), "r"(a3), "r"(b0), "r"(b1))

// ---------------- K0a: x fp32 -> fp16, tiled+swizzled ----------------
__global__ void __launch_bounds__(256) k_cvt_x(const float4* __restrict__ x4) {
    int g = blockIdx.x * blockDim.x + threadIdx.x;       // 16-byte granule id
    if (g >= BT * 128) return;
    int m = g >> 7, gk = g & 127;
    int kt = gk >> 2, j = gk & 3;
    float4 v0 = x4[(size_t)g * 2];
    float4 v1 = x4[(size_t)g * 2 + 1];
    __half2 h0 = __floats2half2_rn(v0.x, v0.y), h1 = __floats2half2_rn(v0.z, v0.w);
    __half2 h2 = __floats2half2_rn(v1.x, v1.y), h3 = __floats2half2_rn(v1.z, v1.w);
    uint4 u;
    u.x = *(uint32_t*)&h0; u.y = *(uint32_t*)&h1;
    u.z = *(uint32_t*)&h2; u.w = *(uint32_t*)&h3;
    int r = m & 127;
    size_t off = ((size_t)((m >> 7) * 32 + kt) * 128 + r) * 32
               + (size_t)(((j + (r >> 1)) & 3) * 8);
    *(uint4*)(g_xh + off) = u;
}

// ---------------- K0b: W[D,2D] -> W^T fp16, tiled+swizzled ----------------
__global__ void k_wt(const float* __restrict__ W) {
    __shared__ float tile[32][33];
    int e0 = blockIdx.x * 32, d0 = blockIdx.y * 32;
    int tx = threadIdx.x, ty = threadIdx.y;
#pragma unroll
    for (int jj = 0; jj < 4; ++jj)
        tile[ty + 8 * jj][tx] = W[(size_t)(d0 + ty + 8 * jj) * N2 + e0 + tx];
    __syncthreads();
#pragma unroll
    for (int jj = 0; jj < 4; ++jj) {
        int e = e0 + ty + 8 * jj;
        int d = d0 + tx;
        int jblk  = (e < 1024) ? (e >> 6) : ((e - 1024) >> 6);
        int rowIn = (e < 1024) ? (e & 63) : (64 + (e & 63));
        int kt = d >> 5, kk = d & 31;
        int jg = kk >> 3, bb = kk & 7;
        size_t off = ((size_t)(jblk * 32 + kt) * 128 + rowIn) * 32
                   + (size_t)(((jg + (rowIn >> 1)) & 3) * 8 + bb);
        g_wt[off] = __float2half_rn(tile[tx][ty + 8 * jj]);
    }
}

// ---------------- K1: HMMA GEMM (4 warps, m64n64 warp tiles) + gates + scan ----------------
static constexpr int SLOT_B   = 16384;               // A 8KB + B 8KB per kt
static constexpr int NBUF     = 6;
static constexpr int MBAR_OFF = NBUF * SLOT_B;       // 98304
static constexpr int SMEM_EPI = 2 * 128 * 72 * 4;
static constexpr int SMEM_DYN = (MBAR_OFF + 64 > SMEM_EPI) ? (MBAR_OFF + 64) : SMEM_EPI;

DEV void gate(float ht, float kk, float& c, float& v) {
    float ek = __expf(kk);
    c = 1.f / (1.f + ek);                   // sigmoid(-k)
    float z = 1.f - c;                      // sigmoid(k)
    float g = (ht >= 0.f) ? (ht + 0.5f) : (1.f / (1.f + __expf(-ht)));
    v = z * g;
}

__global__ void __launch_bounds__(128) k_gemm(const float* __restrict__ bias) {
    extern __shared__ char smem[];
    uint32_t sb = smem_u32(smem);
    int tid = threadIdx.x;
    int wid = tid >> 5, lane = tid & 31;
    int wm = wid & 1, wn = wid >> 1;        // 2m x 2n warp grid, warp tile m64 x n64
    int mt = blockIdx.y;                    // m-tile (128 rows)
    int jb = blockIdx.x;                    // j block (64 pairs)
    int m0 = mt * 128, j0 = jb * 64;

    const __half* Asrc = g_xh + (size_t)mt * 32 * 4096;
    const __half* Bsrc = g_wt + (size_t)jb * 32 * 4096;

    if (tid == 0) {
#pragma unroll
        for (int s = 0; s < NBUF; ++s) MBAR_INIT(sb + MBAR_OFF + 8 * s, 1);
        FENCE_ASYNC();
    }
    __syncthreads();
    if (tid == 0) {
#pragma unroll
        for (int kt = 0; kt < 4; ++kt) {          // prefetch distance 4
            uint32_t mb = sb + MBAR_OFF + 8 * (kt % NBUF);
            MBAR_EXPECT_TX(mb, 16384);
            BULK_G2S(sb + (kt % NBUF) * SLOT_B,        Asrc + (size_t)kt * 4096, 8192, mb);
            BULK_G2S(sb + (kt % NBUF) * SLOT_B + 8192, Bsrc + (size_t)kt * 4096, 8192, mb);
        }
    }

    float acc[4][8][4] = {};               // [m16 tile][n8 tile][frag] = 128 regs

    // ldmatrix lane addressing (swizzled tiled layout)
    int la15 = lane & 15, lhi = lane >> 4;
    int rA = wm * 64 + la15;               // base row of warp's A (mi adds 16)
    uint32_t aRow = (uint32_t)rA * 64;
    uint32_t aCol0 = (uint32_t)(((lhi + (rA >> 1)) & 3) << 4);   // mi*16 rows ≡ 0 mod 8 -> col invariant
    int rB = wn * 64 + ((lane & 7) | (lhi << 3));
    uint32_t bRow = (uint32_t)rB * 64;
    uint32_t bCol0 = (uint32_t)(((((lane >> 3) & 1) + (rB >> 1)) & 3) << 4);

    // paired k-tiles, 6 slots, prefetch distance 4; per-ktq wait immediately
    // before that k-tile's compute (hoisting both waits was a measured
    // regression, R9).
#pragma unroll 1
    for (int kt = 0; kt < 32; kt += 2) {
        __syncthreads();
        if (tid == 0 && kt + 4 < 32) {
#pragma unroll
            for (int q = 4; q < 6; ++q) {
                int sl = (kt + q) % NBUF;
                uint32_t mb = sb + MBAR_OFF + 8 * sl;
                MBAR_EXPECT_TX(mb, 16384);
                BULK_G2S(sb + sl * SLOT_B,        Asrc + (size_t)(kt + q) * 4096, 8192, mb);
                BULK_G2S(sb + sl * SLOT_B + 8192, Bsrc + (size_t)(kt + q) * 4096, 8192, mb);
            }
        }
#pragma unroll
        for (int q = 0; q < 2; ++q) {
            int ktq = kt + q;
            MBAR_WAIT(sb + MBAR_OFF + 8 * (ktq % NBUF), (ktq / NBUF) & 1);
            uint32_t Ab = sb + (uint32_t)(ktq % NBUF) * SLOT_B;
            uint32_t Bb = Ab + 8192;
#pragma unroll
            for (int s = 0; s < 2; ++s) {
                uint32_t aCol = aCol0 ^ (s << 5);
                uint32_t bCol = bCol0 ^ (s << 5);
                uint32_t a[4][4];
#pragma unroll
                for (int mi = 0; mi < 4; ++mi)
                    LDSM4(a[mi][0], a[mi][1], a[mi][2], a[mi][3],
                          Ab + aRow + (uint32_t)mi * 1024 + aCol);
#pragma unroll
                for (int ni = 0; ni < 4; ++ni) {
                    uint32_t b0, b1, b2, b3;
                    LDSM4(b0, b1, b2, b3, Bb + bRow + (uint32_t)ni * 1024 + bCol);
#pragma unroll
                    for (int mi = 0; mi < 4; ++mi) {
                        MMA(acc[mi][2 * ni],     a[mi][0], a[mi][1], a[mi][2], a[mi][3], b0, b1);
                        MMA(acc[mi][2 * ni + 1], a[mi][0], a[mi][1], a[mi][2], a[mi][3], b2, b3);
                    }
                }
            }
        }
    }
    __syncthreads();   // drained; reuse smem for epilogue

    // ---- stage raw projections (+bias); wn=0 -> h~, wn=1 -> k ----
    float* hst = (float*)smem;           // 128 x 72
    float* kst = hst + 128 * 72;
    {
        const float* bptr = bias + (wn ? (1024 + j0) : j0);
        float* dst = wn ? kst : hst;
        int rb = wm * 64 + (lane >> 2);
        int cb = (lane & 3) * 2;
#pragma unroll
        for (int mi = 0; mi < 4; ++mi) {
#pragma unroll
            for (int nj = 0; nj < 8; ++nj) {
                int r = rb + mi * 16;
                int c = nj * 8 + cb;
                float b0v = bptr[c], b1v = bptr[c + 1];
                dst[r * 72 + c]           = acc[mi][nj][0] + b0v;
                dst[r * 72 + c + 1]       = acc[mi][nj][1] + b1v;
                dst[(r + 8) * 72 + c]     = acc[mi][nj][2] + b0v;
                dst[(r + 8) * 72 + c + 1] = acc[mi][nj][3] + b1v;
            }
        }
    }
    __syncthreads();

    // ---- fused gate + full-chunk local scan ----
    // 128 threads: thread (chunk=tid>>6, dcol=tid&63) owns a 64-row column
    // exclusively; gates in-register, writes c/v back in place, scans the
    // whole chunk -> writes g_A/g_Hl directly (no combine step).
    {
        int chunk = tid >> 6;           // 0..1
        int dcol  = tid & 63;
        float a = 1.f, h = 0.f;
#pragma unroll 4
        for (int t = 0; t < 64; ++t) {
            int idx = (chunk * 64 + t) * 72 + dcol;
            float cc, vv;
            gate(hst[idx], kst[idx], cc, vv);
            hst[idx] = cc;
            kst[idx] = vv;
            h = fmaf(cc, h, vv);
            a *= cc;
        }
        int bc = (m0 >> 6) + chunk;
        g_A [bc * D_ + j0 + dcol] = a;
        g_Hl[bc * D_ + j0 + dcol] = h;
    }
    __syncthreads();

    // coalesced fp16 stores of c/v (flat layout)
#pragma unroll
    for (int i = 0; i < 16; ++i) {
        int e = i * 128 + tid;
        int r = e >> 4, q = e & 15;
        size_t go = (size_t)(m0 + r) * D_ + j0 + q * 4;
        float4 cf = *(float4*)(hst + r * 72 + q * 4);
        float4 vf = *(float4*)(kst + r * 72 + q * 4);
        __half2 ca = __floats2half2_rn(cf.x, cf.y), cbh = __floats2half2_rn(cf.z, cf.w);
        __half2 va = __floats2half2_rn(vf.x, vf.y), vb = __floats2half2_rn(vf.z, vf.w);
        uint2 cu, vu;
        cu.x = *(uint32_t*)&ca; cu.y = *(uint32_t*)&cbh;
        vu.x = *(uint32_t*)&va; vu.y = *(uint32_t*)&vb;
        *(uint2*)(g_ch + go) = cu;
        *(uint2*)(g_vh + go) = vu;
    }
}

// ---------------- K3: cross-chunk prefix, warp Kogge-Stone ----------------
__global__ void __launch_bounds__(256) k_scan2() {
    int t = blockIdx.x * blockDim.x + threadIdx.x;
    int w = t >> 5;
    int lane = t & 31;
    int b = w >> 10, d = w & (D_ - 1);
    int bc0 = b * NCH + lane * 2;
    float a0 = g_A [bc0 * D_ + d];
    float h0 = g_Hl[bc0 * D_ + d];
    float a1 = g_A [(bc0 + 1) * D_ + d];
    float h1 = g_Hl[(bc0 + 1) * D_ + d];
    float ia = a0 * a1;
    float ih = fmaf(a1, h0, h1);
#pragma unroll
    for (int off = 1; off < 32; off <<= 1) {
        float ao = __shfl_up_sync(~0u, ia, off);
        float ho = __shfl_up_sync(~0u, ih, off);
        if (lane >= off) {
            ih = fmaf(ia, ho, ih);
            ia = ia * ao;
        }
    }
    float eh = __shfl_up_sync(~0u, ih, 1);
    if (lane == 0) eh = 0.f;
    g_Hp[bc0 * D_ + d]       = eh;
    g_Hp[(bc0 + 1) * D_ + d] = fmaf(a0, eh, h0);
}

// ---------------- K4: replay + residual + LayerNorm (x read from fp16 tiles) ----------------
__global__ void __launch_bounds__(512) k_scan3(
        const float* __restrict__ gamma, const float* __restrict__ beta,
        float* __restrict__ out) {
    __shared__ float2 red[16];
    __shared__ float2 s_mu, s_rs;
    int bc = blockIdx.x;
    int tid = threadIdx.x;
    int lane = tid & 31, wrp = tid >> 5;
    int d2 = tid * 2;
    float h0 = g_Hp[bc * D_ + d2];
    float h1 = g_Hp[bc * D_ + d2 + 1];
    float2 ga = *(const float2*)(gamma + d2);
    float2 be = *(const float2*)(beta + d2);
    size_t base = (size_t)bc * CL * D_ + d2;
    // tiled-x addressing: global row m = bc*64 + t -> tile mt=bc>>1, r=(bc&1)*64+t
    int r0  = (bc & 1) * 64;
    int ktd = d2 >> 5, jg = (d2 >> 3) & 3, bb = d2 & 7;
    const __half* xtile = g_xh + (size_t)((bc >> 1) * 32 + ktd) * 4096;
#pragma unroll 1
    for (int t = 0; t < CL; t += 2) {
        size_t i0 = base + (size_t)t * D_;
        size_t i1 = i0 + D_;
        float2 c0 = __half22float2(*(const __half2*)(g_ch + i0));
        float2 v0 = __half22float2(*(const __half2*)(g_vh + i0));
        float2 c1 = __half22float2(*(const __half2*)(g_ch + i1));
        float2 v1 = __half22float2(*(const __half2*)(g_vh + i1));
        int r = r0 + t;                                   // even
        const __half* pa = xtile + r * 32 + ((jg + (r >> 1)) & 3) * 8 + bb;
        float2 xa = __half22float2(*(const __half2*)pa);
        float2 xb = __half22float2(*(const __half2*)(pa + 32));
        h0 = fmaf(c0.x, h0, v0.x); h1 = fmaf(c0.y, h1, v0.y);
        float ya0 = xa.x + h0, ya1 = xa.y + h1;
        h0 = fmaf(c1.x, h0, v1.x); h1 = fmaf(c1.y, h1, v1.y);
        float yb0 = xb.x + h0, yb1 = xb.y + h1;

        float sx = ya0 + ya1, sy = yb0 + yb1;
#pragma unroll
        for (int o = 16; o; o >>= 1) {
            sx += __shfl_xor_sync(~0u, sx, o);
            sy += __shfl_xor_sync(~0u, sy, o);
        }
        if (lane == 0) red[wrp] = make_float2(sx, sy);
        __syncthreads();
        if (wrp == 0) {
            float2 v = (lane < 16) ? red[lane] : make_float2(0.f, 0.f);
#pragma unroll
            for (int o = 8; o; o >>= 1) {
                v.x += __shfl_xor_sync(~0u, v.x, o);
                v.y += __shfl_xor_sync(~0u, v.y, o);
            }
            if (lane == 0) s_mu = make_float2(v.x * (1.f / 1024.f), v.y * (1.f / 1024.f));
        }
        __syncthreads();
        float mua = s_mu.x, mub = s_mu.y;
        float da0 = ya0 - mua, da1 = ya1 - mua;
        float db0 = yb0 - mub, db1 = yb1 - mub;
        float qx = da0 * da0 + da1 * da1, qy = db0 * db0 + db1 * db1;
#pragma unroll
        for (int o = 16; o; o >>= 1) {
            qx += __shfl_xor_sync(~0u, qx, o);
            qy += __shfl_xor_sync(~0u, qy, o);
        }
        if (lane == 0) red[wrp] = make_float2(qx, qy);
        __syncthreads();
        if (wrp == 0) {
            float2 v = (lane < 16) ? red[lane] : make_float2(0.f, 0.f);
#pragma unroll
            for (int o = 8; o; o >>= 1) {
                v.x += __shfl_xor_sync(~0u, v.x, o);
                v.y += __shfl_xor_sync(~0u, v.y, o);
            }
            if (lane == 0) s_rs = make_float2(rsqrtf(v.x * (1.f / 1024.f) + LN_EPS),
                                              rsqrtf(v.y * (1.f / 1024.f) + LN_EPS));
        }
        __syncthreads();
        float rsa = s_rs.x, rsb = s_rs.y;
        float2 oa, ob;
        oa.x = da0 * rsa * ga.x + be.x;  oa.y = da1 * rsa * ga.y + be.y;
        ob.x = db0 * rsb * ga.x + be.x;  ob.y = db1 * rsb * ga.y + be.y;
        *(float2*)(out + i0) = oa;
        *(float2*)(out + i1) = ob;
    }
}

extern "C" void kernel_launch(void* const* d_in, const int* in_sizes, int n_in,
                              void* d_out, int out_size) {
    const float* x     = (const float*)d_in[0];
    const float* W     = (const float*)d_in[1];
    const float* b     = (const float*)d_in[2];
    const float* gamma = (const float*)d_in[3];
    const float* beta  = (const float*)d_in[4];
    float* out = (float*)d_out;

    cudaFuncSetAttribute(k_gemm, cudaFuncAttributeMaxDynamicSharedMemorySize, SMEM_DYN);

    k_cvt_x<<<(BT * 128) / 256, 256>>>((const float4*)x);
    k_wt<<<dim3(N2 / 32, D_ / 32), dim3(32, 8)>>>(W);
    k_gemm<<<dim3(D_ / 64, BT / 128), 128, SMEM_DYN>>>(b);
    k_scan2<<<(B_ * D_ * 32) / 256, 256>>>();
    k_scan3<<<B_ * NCH, 512>>>(gamma, beta, out);
}

// round 14
// speedup vs baseline: 1.1987x; 1.1987x over previous
#include <cuda_runtime.h>
#include <cuda_fp16.h>
#include <cstdint>

#define DEV __device__ __forceinline__

static constexpr int B_  = 8;
static constexpr int T_  = 4096;
static constexpr int D_  = 1024;
static constexpr int BT  = B_ * T_;        // 32768
static constexpr int N2  = 2 * D_;         // 2048
static constexpr int NCH = 64;
static constexpr int CL  = T_ / NCH;       // 64
static constexpr float LN_EPS = 1e-6f;

// pre-tiled operands: tile (blk, kt) = contiguous 4096 halves (8KB)
// element (row r 0..127, k-half kk 0..31): granule j=kk>>3, b=kk&7
// offset = ((blk*32+kt)*128 + r)*32 + ((j + (r>>1))&3)*8 + b   [halves]
__device__ __align__(16) __half g_xh[(size_t)BT * D_];   // x tiled fp16
__device__ __align__(16) __half g_wt[(size_t)N2 * D_];   // W^T tiled fp16
__device__ __align__(16) __half g_ch[(size_t)BT * D_];   // gate coeff (fp16, flat)
__device__ __align__(16) __half g_vh[(size_t)BT * D_];   // gate value (fp16, flat)
__device__ float g_A [B_ * NCH * D_];
__device__ float g_Hl[B_ * NCH * D_];
__device__ float g_Hp[B_ * NCH * D_];

DEV uint32_t smem_u32(const void* p) {
    uint32_t a;
    asm("{ .reg .u64 t; cvta.to.shared.u64 t, %1; cvt.u32.u64 %0, t; }" : "=r"(a) : "l"(p));
    return a;
}

#define MBAR_INIT(a, c) \
    asm volatile("mbarrier.init.shared.b64 [%0], %1;" :: "r"((uint32_t)(a)), "r"((uint32_t)(c)) : "memory")
#define MBAR_EXPECT_TX(a, tx) \
    asm volatile("mbarrier.arrive.expect_tx.shared.b64 _, [%0], %1;" :: "r"((uint32_t)(a)), "r"((uint32_t)(tx)) : "memory")
#define MBAR_WAIT(a, par) do {                                                             \
    uint32_t _m = (uint32_t)(a); uint32_t _p = (uint32_t)(par); uint32_t _d;               \
    asm volatile("{\n\t.reg .pred p;\n\t"                                                  \
        "mbarrier.try_wait.parity.acquire.cta.shared::cta.b64 p, [%1], %2;\n\t"            \
        "selp.b32 %0, 1, 0, p;\n\t}" : "=r"(_d) : "r"(_m), "r"(_p) : "memory");            \
    if (!_d) {                                                                             \
        asm volatile("{\n\t.reg .pred P1;\n\t"                                             \
            "WL_%=:\n\t"                                                                   \
            "mbarrier.try_wait.parity.acquire.cta.shared::cta.b64 P1, [%0], %1, 0x989680;\n\t" \
            "@P1 bra.uni WD_%=;\n\t bra.uni WL_%=;\n\t WD_%=:\n\t}"                        \
            :: "r"(_m), "r"(_p) : "memory");                                               \
    } } while (0)
#define BULK_G2S(dst, src, bytes, mbar) \
    asm volatile("cp.async.bulk.shared::cta.global.mbarrier::complete_tx::bytes [%0], [%1], %2, [%3];" \
        :: "r"((uint32_t)(dst)), "l"(src), "r"((uint32_t)(bytes)), "r"((uint32_t)(mbar)) : "memory")
#define FENCE_ASYNC() asm volatile("fence.proxy.async.shared::cta;" ::: "memory")

#define LDSM4(r0, r1, r2, r3, addr) \
    asm volatile("ldmatrix.sync.aligned.m8n8.x4.shared.b16 {%0,%1,%2,%3}, [%4];" \
        : "=r"(r0), "=r"(r1), "=r"(r2), "=r"(r3) : "r"(addr))

#define MMA(d, a0, a1, a2, a3, b0, b1) \
    asm volatile("mma.sync.aligned.m16n8k16.row.col.f32.f16.f16.f32 " \
        "{%0,%1,%2,%3}, {%4,%5,%6,%7}, {%8,%9}, {%0,%1,%2,%3};" \
        : "+f"((d)[0]), "+f"((d)[1]), "+f"((d)[2]), "+f"((d)[3]) \
        : "r"(a0), "r"(a1), "r"(a2), "r"(a3), "r"(b0), "r"(b1))

// ---------------- K0a: x fp32 -> fp16, tiled+swizzled ----------------
__global__ void __launch_bounds__(256) k_cvt_x(const float4* __restrict__ x4) {
    int g = blockIdx.x * blockDim.x + threadIdx.x;       // 16-byte granule id
    if (g >= BT * 128) return;
    int m = g >> 7, gk = g & 127;
    int kt = gk >> 2, j = gk & 3;
    float4 v0 = x4[(size_t)g * 2];
    float4 v1 = x4[(size_t)g * 2 + 1];
    __half2 h0 = __floats2half2_rn(v0.x, v0.y), h1 = __floats2half2_rn(v0.z, v0.w);
    __half2 h2 = __floats2half2_rn(v1.x, v1.y), h3 = __floats2half2_rn(v1.z, v1.w);
    uint4 u;
    u.x = *(uint32_t*)&h0; u.y = *(uint32_t*)&h1;
    u.z = *(uint32_t*)&h2; u.w = *(uint32_t*)&h3;
    int r = m & 127;
    size_t off = ((size_t)((m >> 7) * 32 + kt) * 128 + r) * 32
               + (size_t)(((j + (r >> 1)) & 3) * 8);
    *(uint4*)(g_xh + off) = u;
}

// ---------------- K0b: W[D,2D] -> W^T fp16, tiled+swizzled ----------------
__global__ void k_wt(const float* __restrict__ W) {
    __shared__ float tile[32][33];
    int e0 = blockIdx.x * 32, d0 = blockIdx.y * 32;
    int tx = threadIdx.x, ty = threadIdx.y;
#pragma unroll
    for (int jj = 0; jj < 4; ++jj)
        tile[ty + 8 * jj][tx] = W[(size_t)(d0 + ty + 8 * jj) * N2 + e0 + tx];
    __syncthreads();
#pragma unroll
    for (int jj = 0; jj < 4; ++jj) {
        int e = e0 + ty + 8 * jj;
        int d = d0 + tx;
        int jblk  = (e < 1024) ? (e >> 6) : ((e - 1024) >> 6);
        int rowIn = (e < 1024) ? (e & 63) : (64 + (e & 63));
        int kt = d >> 5, kk = d & 31;
        int jg = kk >> 3, bb = kk & 7;
        size_t off = ((size_t)(jblk * 32 + kt) * 128 + rowIn) * 32
                   + (size_t)(((jg + (rowIn >> 1)) & 3) * 8 + bb);
        g_wt[off] = __float2half_rn(tile[tx][ty + 8 * jj]);
    }
}

// ---------------- K1: HMMA GEMM (6-slot bulk pipeline) + gates + local scan ----------------
static constexpr int SLOT_B   = 16384;               // A 8KB + B 8KB per kt
static constexpr int NBUF     = 6;
static constexpr int MBAR_OFF = NBUF * SLOT_B;       // 98304
static constexpr int SMEM_EPI = 2 * 128 * 72 * 4 + 2048;
static constexpr int SMEM_DYN = (MBAR_OFF + 64 > SMEM_EPI) ? (MBAR_OFF + 64) : SMEM_EPI;

DEV void gate(float ht, float kk, float& c, float& v) {
    float ek = __expf(kk);
    c = 1.f / (1.f + ek);                   // sigmoid(-k)
    float z = 1.f - c;                      // sigmoid(k)
    float g = (ht >= 0.f) ? (ht + 0.5f) : (1.f / (1.f + __expf(-ht)));
    v = z * g;
}

__global__ void __launch_bounds__(256) k_gemm(const float* __restrict__ bias) {
    extern __shared__ char smem[];
    uint32_t sb = smem_u32(smem);
    int tid = threadIdx.x;
    int wid = tid >> 5, lane = tid & 31;
    int wm = wid & 3, wn = wid >> 2;        // 4m x 2n warp grid, warp tile m32 x n64
    int mt = blockIdx.y;                    // m-tile (128 rows)
    int jb = blockIdx.x;                    // j block (64 pairs)
    int m0 = mt * 128, j0 = jb * 64;

    const __half* Asrc = g_xh + (size_t)mt * 32 * 4096;
    const __half* Bsrc = g_wt + (size_t)jb * 32 * 4096;

    if (tid == 0) {
#pragma unroll
        for (int s = 0; s < NBUF; ++s) MBAR_INIT(sb + MBAR_OFF + 8 * s, 1);
        FENCE_ASYNC();
    }
    __syncthreads();
    if (tid == 0) {
#pragma unroll
        for (int kt = 0; kt < 4; ++kt) {          // prefetch distance 4
            uint32_t mb = sb + MBAR_OFF + 8 * (kt % NBUF);
            MBAR_EXPECT_TX(mb, 16384);
            BULK_G2S(sb + (kt % NBUF) * SLOT_B,        Asrc + (size_t)kt * 4096, 8192, mb);
            BULK_G2S(sb + (kt % NBUF) * SLOT_B + 8192, Bsrc + (size_t)kt * 4096, 8192, mb);
        }
    }

    float acc[2][8][4] = {};

    // ldmatrix lane addressing (swizzled tiled layout)
    int la15 = lane & 15, lhi = lane >> 4;
    int rA = wm * 32 + la15;
    uint32_t aRow = (uint32_t)rA * 64;
    uint32_t aCol0 = (uint32_t)(((lhi + (rA >> 1)) & 3) << 4);          // s=0
    int rB = wn * 64 + ((lane & 7) | (lhi << 3));
    uint32_t bRow = (uint32_t)rB * 64;
    uint32_t bCol0 = (uint32_t)(((((lane >> 3) & 1) + (rB >> 1)) & 3) << 4);

    // paired k-tiles, 6 slots, prefetch distance 4: at the top of pair
    // (kt,kt+1) issue copies for kt+4/kt+5. Per-ktq wait sits immediately
    // before that k-tile's compute (kt's compute overlaps kt+1's copy —
    // hoisting both waits to the pair top was a measured regression, R9).
#pragma unroll 1
    for (int kt = 0; kt < 32; kt += 2) {
        __syncthreads();
        if (tid == 0 && kt + 4 < 32) {
#pragma unroll
            for (int q = 4; q < 6; ++q) {
                int sl = (kt + q) % NBUF;
                uint32_t mb = sb + MBAR_OFF + 8 * sl;
                MBAR_EXPECT_TX(mb, 16384);
                BULK_G2S(sb + sl * SLOT_B,        Asrc + (size_t)(kt + q) * 4096, 8192, mb);
                BULK_G2S(sb + sl * SLOT_B + 8192, Bsrc + (size_t)(kt + q) * 4096, 8192, mb);
            }
        }
#pragma unroll
        for (int q = 0; q < 2; ++q) {
            int ktq = kt + q;
            MBAR_WAIT(sb + MBAR_OFF + 8 * (ktq % NBUF), (ktq / NBUF) & 1);
            uint32_t Ab = sb + (uint32_t)(ktq % NBUF) * SLOT_B;
            uint32_t Bb = Ab + 8192;
#pragma unroll
            for (int s = 0; s < 2; ++s) {
                uint32_t aCol = aCol0 ^ (s << 5);
                uint32_t bCol = bCol0 ^ (s << 5);
                uint32_t a[2][4];
#pragma unroll
                for (int mi = 0; mi < 2; ++mi)
                    LDSM4(a[mi][0], a[mi][1], a[mi][2], a[mi][3],
                          Ab + aRow + (uint32_t)mi * 1024 + aCol);
#pragma unroll
                for (int ni = 0; ni < 4; ++ni) {
                    uint32_t b0, b1, b2, b3;
                    LDSM4(b0, b1, b2, b3, Bb + bRow + (uint32_t)ni * 1024 + bCol);
#pragma unroll
                    for (int mi = 0; mi < 2; ++mi) {
                        MMA(acc[mi][2 * ni],     a[mi][0], a[mi][1], a[mi][2], a[mi][3], b0, b1);
                        MMA(acc[mi][2 * ni + 1], a[mi][0], a[mi][1], a[mi][2], a[mi][3], b2, b3);
                    }
                }
            }
        }
    }
    __syncthreads();   // drained; reuse smem for epilogue

    // ---- stage raw projections (+bias); wn=0 -> h~, wn=1 -> k ----
    float* hst = (float*)smem;           // 128 x 72
    float* kst = hst + 128 * 72;
    float* sA  = kst + 128 * 72;         // 256 seg aggregates
    float* sH  = sA + 256;
    {
        const float* bptr = bias + (wn ? (1024 + j0) : j0);
        float* dst = wn ? kst : hst;
        int rb = wm * 32 + (lane >> 2);
        int cb = (lane & 3) * 2;
#pragma unroll
        for (int mi = 0; mi < 2; ++mi) {
#pragma unroll
            for (int nj = 0; nj < 8; ++nj) {
                int r = rb + mi * 16;
                int c = nj * 8 + cb;
                float b0v = bptr[c], b1v = bptr[c + 1];
                dst[r * 72 + c]           = acc[mi][nj][0] + b0v;
                dst[r * 72 + c + 1]       = acc[mi][nj][1] + b1v;
                dst[(r + 8) * 72 + c]     = acc[mi][nj][2] + b0v;
                dst[(r + 8) * 72 + c + 1] = acc[mi][nj][3] + b1v;
            }
        }
    }
    __syncthreads();

    // ---- fused gate + local scan phase 1 ----
    // Each thread owns (seg of 32 rows, one d-column) exclusively: gate each
    // element in-register, write c/v back in place, accumulate the scan.
    {
        int seg  = tid >> 6;            // (chunk<<1)|half
        int dcol = tid & 63;
        int rs = seg * 32;
        float a = 1.f, h = 0.f;
#pragma unroll 4
        for (int t = 0; t < 32; ++t) {
            int idx = (rs + t) * 72 + dcol;
            float cc, vv;
            gate(hst[idx], kst[idx], cc, vv);
            hst[idx] = cc;
            kst[idx] = vv;
            h = fmaf(cc, h, vv);
            a *= cc;
        }
        sA[tid] = a; sH[tid] = h;
    }
    __syncthreads();

    // coalesced fp16 stores of c/v (flat layout)
#pragma unroll
    for (int i = 0; i < 8; ++i) {
        int e = i * 256 + tid;
        int r = e >> 4, q = e & 15;
        size_t go = (size_t)(m0 + r) * D_ + j0 + q * 4;
        float4 cf = *(float4*)(hst + r * 72 + q * 4);
        float4 vf = *(float4*)(kst + r * 72 + q * 4);
        __half2 ca = __floats2half2_rn(cf.x, cf.y), cbh = __floats2half2_rn(cf.z, cf.w);
        __half2 va = __floats2half2_rn(vf.x, vf.y), vb = __floats2half2_rn(vf.z, vf.w);
        uint2 cu, vu;
        cu.x = *(uint32_t*)&ca; cu.y = *(uint32_t*)&cbh;
        vu.x = *(uint32_t*)&va; vu.y = *(uint32_t*)&vb;
        *(uint2*)(g_ch + go) = cu;
        *(uint2*)(g_vh + go) = vu;
    }

    // local scan, phase 2: combine halves -> chunk aggregates (sA/sH written
    // before the last sync; safe to read here)
    if (tid < 128) {
        int chunk = tid >> 6, dcol = tid & 63;
        float aLo = sA[chunk * 128 + dcol],      hLo = sH[chunk * 128 + dcol];
        float aHi = sA[chunk * 128 + 64 + dcol], hHi = sH[chunk * 128 + 64 + dcol];
        int bc = (m0 >> 6) + chunk;
        g_A [bc * D_ + j0 + dcol] = aLo * aHi;
        g_Hl[bc * D_ + j0 + dcol] = fmaf(aHi, hLo, hHi);
    }
}

// ---------------- K3: cross-chunk prefix, warp Kogge-Stone ----------------
__global__ void __launch_bounds__(256) k_scan2() {
    int t = blockIdx.x * blockDim.x + threadIdx.x;
    int w = t >> 5;
    int lane = t & 31;
    int b = w >> 10, d = w & (D_ - 1);
    int bc0 = b * NCH + lane * 2;
    float a0 = g_A [bc0 * D_ + d];
    float h0 = g_Hl[bc0 * D_ + d];
    float a1 = g_A [(bc0 + 1) * D_ + d];
    float h1 = g_Hl[(bc0 + 1) * D_ + d];
    float ia = a0 * a1;
    float ih = fmaf(a1, h0, h1);
#pragma unroll
    for (int off = 1; off < 32; off <<= 1) {
        float ao = __shfl_up_sync(~0u, ia, off);
        float ho = __shfl_up_sync(~0u, ih, off);
        if (lane >= off) {
            ih = fmaf(ia, ho, ih);
            ia = ia * ao;
        }
    }
    float eh = __shfl_up_sync(~0u, ih, 1);
    if (lane == 0) eh = 0.f;
    g_Hp[bc0 * D_ + d]       = eh;
    g_Hp[(bc0 + 1) * D_ + d] = fmaf(a0, eh, h0);
}

// ---------------- K4: replay + residual + LayerNorm (software-pipelined loads) ----------------
__global__ void __launch_bounds__(512) k_scan3(
        const float* __restrict__ gamma, const float* __restrict__ beta,
        float* __restrict__ out) {
    __shared__ float2 red[16];
    __shared__ float2 s_mu, s_rs;
    int bc = blockIdx.x;
    int tid = threadIdx.x;
    int lane = tid & 31, wrp = tid >> 5;
    int d2 = tid * 2;
    float h0 = g_Hp[bc * D_ + d2];
    float h1 = g_Hp[bc * D_ + d2 + 1];
    float2 ga = *(const float2*)(gamma + d2);
    float2 be = *(const float2*)(beta + d2);
    size_t base = (size_t)bc * CL * D_ + d2;
    // tiled-x addressing: global row m = bc*64 + t -> tile mt=bc>>1, r=(bc&1)*64+t
    int r0  = (bc & 1) * 64;
    int ktd = d2 >> 5, jg = (d2 >> 3) & 3, bb = d2 & 7;
    const __half* xtile = g_xh + (size_t)((bc >> 1) * 32 + ktd) * 4096;

    // preload iteration 0
    __half2 c0h = *(const __half2*)(g_ch + base);
    __half2 v0h = *(const __half2*)(g_vh + base);
    __half2 c1h = *(const __half2*)(g_ch + base + D_);
    __half2 v1h = *(const __half2*)(g_vh + base + D_);
    const __half* pa0 = xtile + r0 * 32 + ((jg + (r0 >> 1)) & 3) * 8 + bb;
    __half2 xah = *(const __half2*)pa0;
    __half2 xbh = *(const __half2*)(pa0 + 32);

#pragma unroll 1
    for (int t = 0; t < CL; t += 2) {
        size_t i0 = base + (size_t)t * D_;
        size_t i1 = i0 + D_;
        float2 c0 = __half22float2(c0h);
        float2 v0 = __half22float2(v0h);
        float2 c1 = __half22float2(c1h);
        float2 v1 = __half22float2(v1h);
        float2 xa = __half22float2(xah);
        float2 xb = __half22float2(xbh);

        // prefetch iteration t+2 — lands under the two reduction phases below
        if (t + 2 < CL) {
            size_t j0i = base + (size_t)(t + 2) * D_;
            c0h = *(const __half2*)(g_ch + j0i);
            v0h = *(const __half2*)(g_vh + j0i);
            c1h = *(const __half2*)(g_ch + j0i + D_);
            v1h = *(const __half2*)(g_vh + j0i + D_);
            int rn = r0 + t + 2;
            const __half* pn = xtile + rn * 32 + ((jg + (rn >> 1)) & 3) * 8 + bb;
            xah = *(const __half2*)pn;
            xbh = *(const __half2*)(pn + 32);
        }

        h0 = fmaf(c0.x, h0, v0.x); h1 = fmaf(c0.y, h1, v0.y);
        float ya0 = xa.x + h0, ya1 = xa.y + h1;
        h0 = fmaf(c1.x, h0, v1.x); h1 = fmaf(c1.y, h1, v1.y);
        float yb0 = xb.x + h0, yb1 = xb.y + h1;

        float sx = ya0 + ya1, sy = yb0 + yb1;
#pragma unroll
        for (int o = 16; o; o >>= 1) {
            sx += __shfl_xor_sync(~0u, sx, o);
            sy += __shfl_xor_sync(~0u, sy, o);
        }
        if (lane == 0) red[wrp] = make_float2(sx, sy);
        __syncthreads();
        if (wrp == 0) {
            float2 v = (lane < 16) ? red[lane] : make_float2(0.f, 0.f);
#pragma unroll
            for (int o = 8; o; o >>= 1) {
                v.x += __shfl_xor_sync(~0u, v.x, o);
                v.y += __shfl_xor_sync(~0u, v.y, o);
            }
            if (lane == 0) s_mu = make_float2(v.x * (1.f / 1024.f), v.y * (1.f / 1024.f));
        }
        __syncthreads();
        float mua = s_mu.x, mub = s_mu.y;
        float da0 = ya0 - mua, da1 = ya1 - mua;
        float db0 = yb0 - mub, db1 = yb1 - mub;
        float qx = da0 * da0 + da1 * da1, qy = db0 * db0 + db1 * db1;
#pragma unroll
        for (int o = 16; o; o >>= 1) {
            qx += __shfl_xor_sync(~0u, qx, o);
            qy += __shfl_xor_sync(~0u, qy, o);
        }
        if (lane == 0) red[wrp] = make_float2(qx, qy);
        __syncthreads();
        if (wrp == 0) {
            float2 v = (lane < 16) ? red[lane] : make_float2(0.f, 0.f);
#pragma unroll
            for (int o = 8; o; o >>= 1) {
                v.x += __shfl_xor_sync(~0u, v.x, o);
                v.y += __shfl_xor_sync(~0u, v.y, o);
            }
            if (lane == 0) s_rs = make_float2(rsqrtf(v.x * (1.f / 1024.f) + LN_EPS),
                                              rsqrtf(v.y * (1.f / 1024.f) + LN_EPS));
        }
        __syncthreads();
        float rsa = s_rs.x, rsb = s_rs.y;
        float2 oa, ob;
        oa.x = da0 * rsa * ga.x + be.x;  oa.y = da1 * rsa * ga.y + be.y;
        ob.x = db0 * rsb * ga.x + be.x;  ob.y = db1 * rsb * ga.y + be.y;
        *(float2*)(out + i0) = oa;
        *(float2*)(out + i1) = ob;
    }
}

extern "C" void kernel_launch(void* const* d_in, const int* in_sizes, int n_in,
                              void* d_out, int out_size) {
    const float* x     = (const float*)d_in[0];
    const float* W     = (const float*)d_in[1];
    const float* b     = (const float*)d_in[2];
    const float* gamma = (const float*)d_in[3];
    const float* beta  = (const float*)d_in[4];
    float* out = (float*)d_out;

    cudaFuncSetAttribute(k_gemm, cudaFuncAttributeMaxDynamicSharedMemorySize, SMEM_DYN);

    k_cvt_x<<<(BT * 128) / 256, 256>>>((const float4*)x);
    k_wt<<<dim3(N2 / 32, D_ / 32), dim3(32, 8)>>>(W);
    k_gemm<<<dim3(D_ / 64, BT / 128), 256, SMEM_DYN>>>(b);
    k_scan2<<<(B_ * D_ * 32) / 256, 256>>>();
    k_scan3<<<B_ * NCH, 512>>>(gamma, beta, out);
}

// round 15
// speedup vs baseline: 1.2315x; 1.0274x over previous
#include <cuda_runtime.h>
#include <cuda_fp16.h>
#include <cstdint>

#define DEV __device__ __forceinline__

static constexpr int B_  = 8;
static constexpr int T_  = 4096;
static constexpr int D_  = 1024;
static constexpr int BT  = B_ * T_;        // 32768
static constexpr int N2  = 2 * D_;         // 2048
static constexpr int NCH = 64;
static constexpr int CL  = T_ / NCH;       // 64
static constexpr float LN_EPS = 1e-6f;

// pre-tiled operands: tile (blk, kt) = contiguous 4096 halves (8KB)
// element (row r 0..127, k-half kk 0..31): granule j=kk>>3, b=kk&7
// offset = ((blk*32+kt)*128 + r)*32 + ((j + (r>>1))&3)*8 + b   [halves]
__device__ __align__(16) __half g_xh[(size_t)BT * D_];   // x tiled fp16
__device__ __align__(16) __half g_wt[(size_t)N2 * D_];   // W^T tiled fp16
__device__ __align__(16) __half g_ch[(size_t)BT * D_];   // gate coeff (fp16, flat)
__device__ __align__(16) __half g_vh[(size_t)BT * D_];   // gate value (fp16, flat)
__device__ float g_A [B_ * NCH * D_];
__device__ float g_Hl[B_ * NCH * D_];
__device__ float g_Hp[B_ * NCH * D_];

DEV uint32_t smem_u32(const void* p) {
    uint32_t a;
    asm("{ .reg .u64 t; cvta.to.shared.u64 t, %1; cvt.u32.u64 %0, t; }" : "=r"(a) : "l"(p));
    return a;
}

#define MBAR_INIT(a, c) \
    asm volatile("mbarrier.init.shared.b64 [%0], %1;" :: "r"((uint32_t)(a)), "r"((uint32_t)(c)) : "memory")
#define MBAR_EXPECT_TX(a, tx) \
    asm volatile("mbarrier.arrive.expect_tx.shared.b64 _, [%0], %1;" :: "r"((uint32_t)(a)), "r"((uint32_t)(tx)) : "memory")
#define MBAR_WAIT(a, par) do {                                                             \
    uint32_t _m = (uint32_t)(a); uint32_t _p = (uint32_t)(par); uint32_t _d;               \
    asm volatile("{\n\t.reg .pred p;\n\t"                                                  \
        "mbarrier.try_wait.parity.acquire.cta.shared::cta.b64 p, [%1], %2;\n\t"            \
        "selp.b32 %0, 1, 0, p;\n\t}" : "=r"(_d) : "r"(_m), "r"(_p) : "memory");            \
    if (!_d) {                                                                             \
        asm volatile("{\n\t.reg .pred P1;\n\t"                                             \
            "WL_%=:\n\t"                                                                   \
            "mbarrier.try_wait.parity.acquire.cta.shared::cta.b64 P1, [%0], %1, 0x989680;\n\t" \
            "@P1 bra.uni WD_%=;\n\t bra.uni WL_%=;\n\t WD_%=:\n\t}"                        \
            :: "r"(_m), "r"(_p) : "memory");                                               \
    } } while (0)
#define BULK_G2S(dst, src, bytes, mbar) \
    asm volatile("cp.async.bulk.shared::cta.global.mbarrier::complete_tx::bytes [%0], [%1], %2, [%3];" \
        :: "r"((uint32_t)(dst)), "l"(src), "r"((uint32_t)(bytes)), "r"((uint32_t)(mbar)) : "memory")
#define FENCE_ASYNC() asm volatile("fence.proxy.async.shared::cta;" ::: "memory")

#define LDSM4(r0, r1, r2, r3, addr) \
    asm volatile("ldmatrix.sync.aligned.m8n8.x4.shared.b16 {%0,%1,%2,%3}, [%4];" \
        : "=r"(r0), "=r"(r1), "=r"(r2), "=r"(r3) : "r"(addr))

#define MMA(d, a0, a1, a2, a3, b0, b1) \
    asm volatile("mma.sync.aligned.m16n8k16.row.col.f32.f16.f16.f32 " \
        "{%0,%1,%2,%3}, {%4,%5,%6,%7}, {%8,%9}, {%0,%1,%2,%3};" \
        : "+f"((d)[0]), "+f"((d)[1]), "+f"((d)[2]), "+f"((d)[3]) \
        : "r"(a0), "r"(a1), "r"(a2), "r"(a3), "r"(b0), "r"(b1))

// ---------------- K0a: x fp32 -> fp16, tiled+swizzled ----------------
__global__ void __launch_bounds__(256) k_cvt_x(const float4* __restrict__ x4) {
    int g = blockIdx.x * blockDim.x + threadIdx.x;       // 16-byte granule id
    if (g >= BT * 128) return;
    int m = g >> 7, gk = g & 127;
    int kt = gk >> 2, j = gk & 3;
    float4 v0 = x4[(size_t)g * 2];
    float4 v1 = x4[(size_t)g * 2 + 1];
    __half2 h0 = __floats2half2_rn(v0.x, v0.y), h1 = __floats2half2_rn(v0.z, v0.w);
    __half2 h2 = __floats2half2_rn(v1.x, v1.y), h3 = __floats2half2_rn(v1.z, v1.w);
    uint4 u;
    u.x = *(uint32_t*)&h0; u.y = *(uint32_t*)&h1;
    u.z = *(uint32_t*)&h2; u.w = *(uint32_t*)&h3;
    int r = m & 127;
    size_t off = ((size_t)((m >> 7) * 32 + kt) * 128 + r) * 32
               + (size_t)(((j + (r >> 1)) & 3) * 8);
    *(uint4*)(g_xh + off) = u;
}

// ---------------- K0b: W[D,2D] -> W^T fp16, tiled+swizzled ----------------
__global__ void k_wt(const float* __restrict__ W) {
    __shared__ float tile[32][33];
    int e0 = blockIdx.x * 32, d0 = blockIdx.y * 32;
    int tx = threadIdx.x, ty = threadIdx.y;
#pragma unroll
    for (int jj = 0; jj < 4; ++jj)
        tile[ty + 8 * jj][tx] = W[(size_t)(d0 + ty + 8 * jj) * N2 + e0 + tx];
    __syncthreads();
#pragma unroll
    for (int jj = 0; jj < 4; ++jj) {
        int e = e0 + ty + 8 * jj;
        int d = d0 + tx;
        int jblk  = (e < 1024) ? (e >> 6) : ((e - 1024) >> 6);
        int rowIn = (e < 1024) ? (e & 63) : (64 + (e & 63));
        int kt = d >> 5, kk = d & 31;
        int jg = kk >> 3, bb = kk & 7;
        size_t off = ((size_t)(jblk * 32 + kt) * 128 + rowIn) * 32
                   + (size_t)(((jg + (rowIn >> 1)) & 3) * 8 + bb);
        g_wt[off] = __float2half_rn(tile[tx][ty + 8 * jj]);
    }
}

// ---------------- K1: HMMA GEMM (6-slot bulk pipeline) + gates + local scan ----------------
static constexpr int SLOT_B   = 16384;               // A 8KB + B 8KB per kt
static constexpr int NBUF     = 6;
static constexpr int MBAR_OFF = NBUF * SLOT_B;       // 98304
static constexpr int SMEM_EPI = 2 * 128 * 72 * 4 + 2048;
static constexpr int SMEM_DYN = (MBAR_OFF + 64 > SMEM_EPI) ? (MBAR_OFF + 64) : SMEM_EPI;

DEV void gate(float ht, float kk, float& c, float& v) {
    float ek = __expf(kk);
    c = 1.f / (1.f + ek);                   // sigmoid(-k)
    float z = 1.f - c;                      // sigmoid(k)
    float g = (ht >= 0.f) ? (ht + 0.5f) : (1.f / (1.f + __expf(-ht)));
    v = z * g;
}

__global__ void __launch_bounds__(256) k_gemm(const float* __restrict__ bias) {
    extern __shared__ char smem[];
    uint32_t sb = smem_u32(smem);
    int tid = threadIdx.x;
    int wid = tid >> 5, lane = tid & 31;
    int wm = wid & 3, wn = wid >> 2;        // 4m x 2n warp grid, warp tile m32 x n64
    int mt = blockIdx.y;                    // m-tile (128 rows)
    int jb = blockIdx.x;                    // j block (64 pairs)
    int m0 = mt * 128, j0 = jb * 64;

    const __half* Asrc = g_xh + (size_t)mt * 32 * 4096;
    const __half* Bsrc = g_wt + (size_t)jb * 32 * 4096;

    if (tid == 0) {
#pragma unroll
        for (int s = 0; s < NBUF; ++s) MBAR_INIT(sb + MBAR_OFF + 8 * s, 1);
        FENCE_ASYNC();
    }
    __syncthreads();
    if (tid == 0) {
#pragma unroll
        for (int kt = 0; kt < 4; ++kt) {          // prefetch distance 4
            uint32_t mb = sb + MBAR_OFF + 8 * (kt % NBUF);
            MBAR_EXPECT_TX(mb, 16384);
            BULK_G2S(sb + (kt % NBUF) * SLOT_B,        Asrc + (size_t)kt * 4096, 8192, mb);
            BULK_G2S(sb + (kt % NBUF) * SLOT_B + 8192, Bsrc + (size_t)kt * 4096, 8192, mb);
        }
    }

    float acc[2][8][4] = {};

    // ldmatrix lane addressing (swizzled tiled layout)
    int la15 = lane & 15, lhi = lane >> 4;
    int rA = wm * 32 + la15;
    uint32_t aRow = (uint32_t)rA * 64;
    uint32_t aCol0 = (uint32_t)(((lhi + (rA >> 1)) & 3) << 4);          // s=0
    int rB = wn * 64 + ((lane & 7) | (lhi << 3));
    uint32_t bRow = (uint32_t)rB * 64;
    uint32_t bCol0 = (uint32_t)(((((lane >> 3) & 1) + (rB >> 1)) & 3) << 4);

    // paired k-tiles, 6 slots, prefetch distance 4: at the top of pair
    // (kt,kt+1) issue copies for kt+4/kt+5. Per-ktq wait sits immediately
    // before that k-tile's compute (kt's compute overlaps kt+1's copy —
    // hoisting both waits to the pair top was a measured regression, R9).
#pragma unroll 1
    for (int kt = 0; kt < 32; kt += 2) {
        __syncthreads();
        if (tid == 0 && kt + 4 < 32) {
#pragma unroll
            for (int q = 4; q < 6; ++q) {
                int sl = (kt + q) % NBUF;
                uint32_t mb = sb + MBAR_OFF + 8 * sl;
                MBAR_EXPECT_TX(mb, 16384);
                BULK_G2S(sb + sl * SLOT_B,        Asrc + (size_t)(kt + q) * 4096, 8192, mb);
                BULK_G2S(sb + sl * SLOT_B + 8192, Bsrc + (size_t)(kt + q) * 4096, 8192, mb);
            }
        }
#pragma unroll
        for (int q = 0; q < 2; ++q) {
            int ktq = kt + q;
            MBAR_WAIT(sb + MBAR_OFF + 8 * (ktq % NBUF), (ktq / NBUF) & 1);
            uint32_t Ab = sb + (uint32_t)(ktq % NBUF) * SLOT_B;
            uint32_t Bb = Ab + 8192;
#pragma unroll
            for (int s = 0; s < 2; ++s) {
                uint32_t aCol = aCol0 ^ (s << 5);
                uint32_t bCol = bCol0 ^ (s << 5);
                uint32_t a[2][4];
#pragma unroll
                for (int mi = 0; mi < 2; ++mi)
                    LDSM4(a[mi][0], a[mi][1], a[mi][2], a[mi][3],
                          Ab + aRow + (uint32_t)mi * 1024 + aCol);
#pragma unroll
                for (int ni = 0; ni < 4; ++ni) {
                    uint32_t b0, b1, b2, b3;
                    LDSM4(b0, b1, b2, b3, Bb + bRow + (uint32_t)ni * 1024 + bCol);
#pragma unroll
                    for (int mi = 0; mi < 2; ++mi) {
                        MMA(acc[mi][2 * ni],     a[mi][0], a[mi][1], a[mi][2], a[mi][3], b0, b1);
                        MMA(acc[mi][2 * ni + 1], a[mi][0], a[mi][1], a[mi][2], a[mi][3], b2, b3);
                    }
                }
            }
        }
    }
    __syncthreads();   // drained; reuse smem for epilogue

    // ---- stage raw projections (+bias); wn=0 -> h~, wn=1 -> k ----
    float* hst = (float*)smem;           // 128 x 72
    float* kst = hst + 128 * 72;
    float* sA  = kst + 128 * 72;         // 256 seg aggregates
    float* sH  = sA + 256;
    {
        const float* bptr = bias + (wn ? (1024 + j0) : j0);
        float* dst = wn ? kst : hst;
        int rb = wm * 32 + (lane >> 2);
        int cb = (lane & 3) * 2;
#pragma unroll
        for (int mi = 0; mi < 2; ++mi) {
#pragma unroll
            for (int nj = 0; nj < 8; ++nj) {
                int r = rb + mi * 16;
                int c = nj * 8 + cb;
                float b0v = bptr[c], b1v = bptr[c + 1];
                dst[r * 72 + c]           = acc[mi][nj][0] + b0v;
                dst[r * 72 + c + 1]       = acc[mi][nj][1] + b1v;
                dst[(r + 8) * 72 + c]     = acc[mi][nj][2] + b0v;
                dst[(r + 8) * 72 + c + 1] = acc[mi][nj][3] + b1v;
            }
        }
    }
    __syncthreads();

    // ---- fused gate + local scan phase 1 ----
    {
        int seg  = tid >> 6;            // (chunk<<1)|half
        int dcol = tid & 63;
        int rs = seg * 32;
        float a = 1.f, h = 0.f;
#pragma unroll 4
        for (int t = 0; t < 32; ++t) {
            int idx = (rs + t) * 72 + dcol;
            float cc, vv;
            gate(hst[idx], kst[idx], cc, vv);
            hst[idx] = cc;
            kst[idx] = vv;
            h = fmaf(cc, h, vv);
            a *= cc;
        }
        sA[tid] = a; sH[tid] = h;
    }
    __syncthreads();

    // coalesced fp16 stores of c/v (flat layout)
#pragma unroll
    for (int i = 0; i < 8; ++i) {
        int e = i * 256 + tid;
        int r = e >> 4, q = e & 15;
        size_t go = (size_t)(m0 + r) * D_ + j0 + q * 4;
        float4 cf = *(float4*)(hst + r * 72 + q * 4);
        float4 vf = *(float4*)(kst + r * 72 + q * 4);
        __half2 ca = __floats2half2_rn(cf.x, cf.y), cbh = __floats2half2_rn(cf.z, cf.w);
        __half2 va = __floats2half2_rn(vf.x, vf.y), vb = __floats2half2_rn(vf.z, vf.w);
        uint2 cu, vu;
        cu.x = *(uint32_t*)&ca; cu.y = *(uint32_t*)&cbh;
        vu.x = *(uint32_t*)&va; vu.y = *(uint32_t*)&vb;
        *(uint2*)(g_ch + go) = cu;
        *(uint2*)(g_vh + go) = vu;
    }

    // local scan, phase 2: combine halves -> chunk aggregates
    if (tid < 128) {
        int chunk = tid >> 6, dcol = tid & 63;
        float aLo = sA[chunk * 128 + dcol],      hLo = sH[chunk * 128 + dcol];
        float aHi = sA[chunk * 128 + 64 + dcol], hHi = sH[chunk * 128 + 64 + dcol];
        int bc = (m0 >> 6) + chunk;
        g_A [bc * D_ + j0 + dcol] = aLo * aHi;
        g_Hl[bc * D_ + j0 + dcol] = fmaf(aHi, hLo, hHi);
    }
}

// ---------------- K3: cross-chunk prefix, warp Kogge-Stone ----------------
__global__ void __launch_bounds__(256) k_scan2() {
    int t = blockIdx.x * blockDim.x + threadIdx.x;
    int w = t >> 5;
    int lane = t & 31;
    int b = w >> 10, d = w & (D_ - 1);
    int bc0 = b * NCH + lane * 2;
    float a0 = g_A [bc0 * D_ + d];
    float h0 = g_Hl[bc0 * D_ + d];
    float a1 = g_A [(bc0 + 1) * D_ + d];
    float h1 = g_Hl[(bc0 + 1) * D_ + d];
    float ia = a0 * a1;
    float ih = fmaf(a1, h0, h1);
#pragma unroll
    for (int off = 1; off < 32; off <<= 1) {
        float ao = __shfl_up_sync(~0u, ia, off);
        float ho = __shfl_up_sync(~0u, ih, off);
        if (lane >= off) {
            ih = fmaf(ia, ho, ih);
            ia = ia * ao;
        }
    }
    float eh = __shfl_up_sync(~0u, ih, 1);
    if (lane == 0) eh = 0.f;
    g_Hp[bc0 * D_ + d]       = eh;
    g_Hp[(bc0 + 1) * D_ + d] = fmaf(a0, eh, h0);
}

// ---------------- K4: replay + residual + LayerNorm (tiled, warp-per-timestep LN) ----------------
// Phase A: 512 threads run the recurrence for 16 timesteps, stage y in smem.
// Phase B: 16 warps each LN one timestep (warp-local reductions, no block
// barriers). 8 __syncthreads total vs 256 in the per-timestep scheme.
static constexpr int TT = 16;                              // timesteps per tile
static constexpr int S3_YS  = TT * D_;                     // y staging floats
static constexpr int S3_DYN = (S3_YS + 2 * D_) * 4;        // + gamma, beta

__global__ void __launch_bounds__(512) k_scan3(
        const float* __restrict__ gamma, const float* __restrict__ beta,
        float* __restrict__ out) {
    extern __shared__ float sm3[];
    float* ys  = sm3;                 // [TT][1024]
    float* sga = sm3 + S3_YS;
    float* sbe = sga + D_;
    int bc = blockIdx.x;
    int tid = threadIdx.x;
    int lane = tid & 31, wrp = tid >> 5;
    int d2 = tid * 2;

    sga[tid] = gamma[tid];  sga[tid + 512] = gamma[tid + 512];
    sbe[tid] = beta[tid];   sbe[tid + 512] = beta[tid + 512];

    float h0 = g_Hp[bc * D_ + d2];
    float h1 = g_Hp[bc * D_ + d2 + 1];
    size_t base = (size_t)bc * CL * D_ + d2;
    // tiled-x addressing: global row m = bc*64 + t -> tile mt=bc>>1, r=(bc&1)*64+t
    int r0  = (bc & 1) * 64;
    int ktd = d2 >> 5, jg = (d2 >> 3) & 3, bb = d2 & 7;
    const __half* xtile = g_xh + (size_t)((bc >> 1) * 32 + ktd) * 4096;
    __syncthreads();                  // gamma/beta visible

#pragma unroll 1
    for (int t0 = 0; t0 < CL; t0 += TT) {
        // ---- Phase A: recurrence + residual into smem ----
#pragma unroll
        for (int tt = 0; tt < TT; ++tt) {
            int t = t0 + tt;
            size_t idx = base + (size_t)t * D_;
            float2 cf = __half22float2(*(const __half2*)(g_ch + idx));
            float2 vf = __half22float2(*(const __half2*)(g_vh + idx));
            int r = r0 + t;
            const __half* px = xtile + r * 32 + ((jg + (r >> 1)) & 3) * 8 + bb;
            float2 xx = __half22float2(*(const __half2*)px);
            h0 = fmaf(cf.x, h0, vf.x);
            h1 = fmaf(cf.y, h1, vf.y);
            float2 y2 = make_float2(xx.x + h0, xx.y + h1);
            *(float2*)(ys + tt * D_ + d2) = y2;
        }
        __syncthreads();

        // ---- Phase B: warp wrp LNs timestep t0+wrp ----
        {
            float yv[32];
            float s = 0.f;
            const float* yrow = ys + wrp * D_;
#pragma unroll
            for (int i = 0; i < 32; ++i) {
                yv[i] = yrow[i * 32 + lane];
                s += yv[i];
            }
#pragma unroll
            for (int o = 16; o; o >>= 1) s += __shfl_xor_sync(~0u, s, o);
            float mu = s * (1.f / 1024.f);
            float q = 0.f;
#pragma unroll
            for (int i = 0; i < 32; ++i) {
                float dd = yv[i] - mu;
                q = fmaf(dd, dd, q);
            }
#pragma unroll
            for (int o = 16; o; o >>= 1) q += __shfl_xor_sync(~0u, q, o);
            float rs = rsqrtf(q * (1.f / 1024.f) + LN_EPS);
            float* op = out + ((size_t)bc * CL + (t0 + wrp)) * D_;
#pragma unroll
            for (int i = 0; i < 32; ++i) {
                int d = i * 32 + lane;
                op[d] = (yv[i] - mu) * rs * sga[d] + sbe[d];
            }
        }
        __syncthreads();              // ys free for next tile
    }
}

extern "C" void kernel_launch(void* const* d_in, const int* in_sizes, int n_in,
                              void* d_out, int out_size) {
    const float* x     = (const float*)d_in[0];
    const float* W     = (const float*)d_in[1];
    const float* b     = (const float*)d_in[2];
    const float* gamma = (const float*)d_in[3];
    const float* beta  = (const float*)d_in[4];
    float* out = (float*)d_out;

    cudaFuncSetAttribute(k_gemm, cudaFuncAttributeMaxDynamicSharedMemorySize, SMEM_DYN);
    cudaFuncSetAttribute(k_scan3, cudaFuncAttributeMaxDynamicSharedMemorySize, S3_DYN);

    k_cvt_x<<<(BT * 128) / 256, 256>>>((const float4*)x);
    k_wt<<<dim3(N2 / 32, D_ / 32), dim3(32, 8)>>>(W);
    k_gemm<<<dim3(D_ / 64, BT / 128), 256, SMEM_DYN>>>(b);
    k_scan2<<<(B_ * D_ * 32) / 256, 256>>>();
    k_scan3<<<B_ * NCH, 512, S3_DYN>>>(gamma, beta, out);
}